// round 3
// baseline (speedup 1.0000x reference)
#include <cuda_runtime.h>
#include <math.h>

#define NB   4
#define DIMD 1024
#define PQ   512
#define NH   16
#define PD   64

// ---- static device scratch (no allocations allowed) ----
static __device__ float g_xds  [NB * PQ * DIMD];         // pooled x  [2048][1024]
static __device__ float g_q    [NB * PQ * DIMD];
static __device__ float g_k    [NB * PQ * DIMD];
static __device__ float g_pA   [DIMD];
static __device__ float g_pB   [DIMD];
static __device__ float g_ypart[8 * 2048 * 128];         // K-split partials, [s][row][n] n: 0-63 yq, 64-127 yk
static __device__ float g_RqA  [NB * PQ * PD];
static __device__ float g_RqB  [NB * PQ * PD];
static __device__ float g_CkA  [NB * PQ * PD];
static __device__ float g_CkB  [NB * PQ * PD];

// ---------------- 1) avg-pool (POOL=4) ----------------
__global__ void k_pool(const float* __restrict__ x) {
    int gid = blockIdx.x * blockDim.x + threadIdx.x;  // 2048*256
    int d4 = gid & 255;
    int bp = gid >> 8;
    const float4* xin = reinterpret_cast<const float4*>(x);
    size_t base = (size_t)bp * 4 * 256 + d4;
    float4 r0 = xin[base];
    float4 r1 = xin[base + 256];
    float4 r2 = xin[base + 512];
    float4 r3 = xin[base + 768];
    float4 o;
    o.x = (r0.x + r1.x + r2.x + r3.x) * 0.25f;
    o.y = (r0.y + r1.y + r2.y + r3.y) * 0.25f;
    o.z = (r0.z + r1.z + r2.z + r3.z) * 0.25f;
    o.w = (r0.w + r1.w + r2.w + r3.w) * 0.25f;
    reinterpret_cast<float4*>(g_xds)[(size_t)bp * 256 + d4] = o;
}

// ---------------- 2) pos_enc collapse ----------------
__global__ void k_posenc(const float* __restrict__ Wpos, const float* __restrict__ bpos) {
    int hc = blockIdx.x * blockDim.x + threadIdx.x;
    if (hc >= DIMD) return;
    float s1 = 0.f, s2 = 0.f;
#pragma unroll
    for (int j = 0; j < 32; j++) s1 += Wpos[hc * 64 + j];
#pragma unroll
    for (int j = 32; j < 64; j++) s2 += Wpos[hc * 64 + j];
    g_pA[hc] = s1 - s2 + bpos[hc];   // p < 511
    g_pB[hc] = s1 + bpos[hc];        // p == 511
}

// ---------------- 3) q/k projection SGEMM: [2048x1024]@[1024x1024]^T ----------------
// 128x128 tile, bk=16, vectorized float4 smem reads (contiguous 4+4 micro-tile).
__global__ __launch_bounds__(256) void k_proj(const float* __restrict__ Wq,
                                              const float* __restrict__ Wk) {
    __shared__ float As[16][132];
    __shared__ float Bs[16][132];
    const float* __restrict__ A = g_xds;
    const float* __restrict__ B = blockIdx.z ? Wk : Wq;
    float* __restrict__ C = blockIdx.z ? g_k : g_q;
    int bm = blockIdx.y * 128;
    int bn = blockIdx.x * 128;
    int tid = threadIdx.x;
    int lr = tid >> 1;
    int lc = (tid & 1) * 8;
    int tx = tid & 15;
    int ty = tid >> 4;
    float acc[8][8];
#pragma unroll
    for (int i = 0; i < 8; i++)
#pragma unroll
        for (int j = 0; j < 8; j++) acc[i][j] = 0.f;

    const float* aptr = A + (size_t)(bm + lr) * DIMD + lc;
    const float* bptr = B + (size_t)(bn + lr) * DIMD + lc;

    for (int k0 = 0; k0 < DIMD; k0 += 16) {
        float4 a0 = *(const float4*)(aptr + k0);
        float4 a1 = *(const float4*)(aptr + k0 + 4);
        float4 b0 = *(const float4*)(bptr + k0);
        float4 b1 = *(const float4*)(bptr + k0 + 4);
        __syncthreads();
        As[lc + 0][lr] = a0.x; As[lc + 1][lr] = a0.y;
        As[lc + 2][lr] = a0.z; As[lc + 3][lr] = a0.w;
        As[lc + 4][lr] = a1.x; As[lc + 5][lr] = a1.y;
        As[lc + 6][lr] = a1.z; As[lc + 7][lr] = a1.w;
        Bs[lc + 0][lr] = b0.x; Bs[lc + 1][lr] = b0.y;
        Bs[lc + 2][lr] = b0.z; Bs[lc + 3][lr] = b0.w;
        Bs[lc + 4][lr] = b1.x; Bs[lc + 5][lr] = b1.y;
        Bs[lc + 6][lr] = b1.z; Bs[lc + 7][lr] = b1.w;
        __syncthreads();
#pragma unroll
        for (int kk = 0; kk < 16; kk++) {
            float4 af0 = *(const float4*)&As[kk][ty * 4];
            float4 af1 = *(const float4*)&As[kk][64 + ty * 4];
            float4 bf0 = *(const float4*)&Bs[kk][tx * 4];
            float4 bf1 = *(const float4*)&Bs[kk][64 + tx * 4];
            float av[8] = {af0.x, af0.y, af0.z, af0.w, af1.x, af1.y, af1.z, af1.w};
            float bv[8] = {bf0.x, bf0.y, bf0.z, bf0.w, bf1.x, bf1.y, bf1.z, bf1.w};
#pragma unroll
            for (int i = 0; i < 8; i++)
#pragma unroll
                for (int j = 0; j < 8; j++) acc[i][j] += av[i] * bv[j];
        }
    }
#pragma unroll
    for (int i = 0; i < 8; i++) {
        int r = bm + (i < 4 ? ty * 4 + i : 64 + ty * 4 + (i - 4));
        float4 v0 = make_float4(acc[i][0], acc[i][1], acc[i][2], acc[i][3]);
        float4 v1 = make_float4(acc[i][4], acc[i][5], acc[i][6], acc[i][7]);
        *(float4*)&C[(size_t)r * DIMD + bn + tx * 4]      = v0;
        *(float4*)&C[(size_t)r * DIMD + bn + 64 + tx * 4] = v1;
    }
}

// ---------------- 4) y partials: gelu(x_ds) @ [Wyq;Wyk]^T, K split 8 ways ----------------
__global__ __launch_bounds__(256) void k_y(const float* __restrict__ Wyq,
                                           const float* __restrict__ Wyk) {
    __shared__ float As[16][132];
    __shared__ float Bs[16][132];
    int ks = blockIdx.x;             // K slice 0..7 (128 each)
    int bm = blockIdx.y * 128;
    int tid = threadIdx.x;
    int lr = tid >> 1;
    int lc = (tid & 1) * 8;
    int tx = tid & 15;
    int ty = tid >> 4;
    float acc[8][8];
#pragma unroll
    for (int i = 0; i < 8; i++)
#pragma unroll
        for (int j = 0; j < 8; j++) acc[i][j] = 0.f;

    const float* aptr = g_xds + (size_t)(bm + lr) * DIMD + ks * 128 + lc;
    const float* brow = (lr < 64) ? (Wyq + (size_t)lr * DIMD) : (Wyk + (size_t)(lr - 64) * DIMD);
    const float* bptr = brow + ks * 128 + lc;

    for (int k0 = 0; k0 < 128; k0 += 16) {
        float4 a0 = *(const float4*)(aptr + k0);
        float4 a1 = *(const float4*)(aptr + k0 + 4);
        float4 b0 = *(const float4*)(bptr + k0);
        float4 b1 = *(const float4*)(bptr + k0 + 4);
        // exact gelu on A elements
        float av8[8] = {a0.x, a0.y, a0.z, a0.w, a1.x, a1.y, a1.z, a1.w};
#pragma unroll
        for (int e = 0; e < 8; e++)
            av8[e] = 0.5f * av8[e] * (1.f + erff(av8[e] * 0.70710678118654752f));
        __syncthreads();
#pragma unroll
        for (int e = 0; e < 8; e++) As[lc + e][lr] = av8[e];
        Bs[lc + 0][lr] = b0.x; Bs[lc + 1][lr] = b0.y;
        Bs[lc + 2][lr] = b0.z; Bs[lc + 3][lr] = b0.w;
        Bs[lc + 4][lr] = b1.x; Bs[lc + 5][lr] = b1.y;
        Bs[lc + 6][lr] = b1.z; Bs[lc + 7][lr] = b1.w;
        __syncthreads();
#pragma unroll
        for (int kk = 0; kk < 16; kk++) {
            float4 af0 = *(const float4*)&As[kk][ty * 4];
            float4 af1 = *(const float4*)&As[kk][64 + ty * 4];
            float4 bf0 = *(const float4*)&Bs[kk][tx * 4];
            float4 bf1 = *(const float4*)&Bs[kk][64 + tx * 4];
            float av[8] = {af0.x, af0.y, af0.z, af0.w, af1.x, af1.y, af1.z, af1.w};
            float bv[8] = {bf0.x, bf0.y, bf0.z, bf0.w, bf1.x, bf1.y, bf1.z, bf1.w};
#pragma unroll
            for (int i = 0; i < 8; i++)
#pragma unroll
                for (int j = 0; j < 8; j++) acc[i][j] += av[i] * bv[j];
        }
    }
#pragma unroll
    for (int i = 0; i < 8; i++) {
        int r = bm + (i < 4 ? ty * 4 + i : 64 + ty * 4 + (i - 4));
        float4 v0 = make_float4(acc[i][0], acc[i][1], acc[i][2], acc[i][3]);
        float4 v1 = make_float4(acc[i][4], acc[i][5], acc[i][6], acc[i][7]);
        *(float4*)&g_ypart[((size_t)ks * 2048 + r) * 128 + tx * 4]      = v0;
        *(float4*)&g_ypart[((size_t)ks * 2048 + r) * 128 + 64 + tx * 4] = v1;
    }
}

// ---------------- 5) row/col correction tensors (folds y-partial reduction) ----------------
__global__ __launch_bounds__(64) void k_scalars(const float* __restrict__ qbias,
                                                const float* __restrict__ kbias,
                                                const float* __restrict__ Wout,
                                                const float* __restrict__ bout) {
    __shared__ float sA[16], sB[16];
    int row = blockIdx.x;          // b*512 + p
    int z = blockIdx.y;            // 0: Rq (from q), 1: Ck (from k)
    const float* src  = z ? g_k : g_q;
    const float* bias = z ? kbias : qbias;
    int t = threadIdx.x;
    if (t < 16) {
        float a = 0.f, bs = 0.f;
        int base = t * 64;
        for (int c = 0; c < 64; c++) {
            float v = src[(size_t)row * DIMD + base + c] + bias[base + c];
            a  += v * g_pA[base + c];
            bs += v * g_pB[base + c];
        }
        sA[t] = a; sB[t] = bs;
    }
    __syncthreads();
    float rA = 0.f, rB = 0.f;
#pragma unroll
    for (int h = 0; h < 16; h++) {
        float w = Wout[t * 16 + h];
        rA += sA[h] * w;
        rB += sB[h] * w;
    }
    float yv = 0.f;
#pragma unroll
    for (int s = 0; s < 8; s++)
        yv += g_ypart[((size_t)s * 2048 + row) * 128 + z * 64 + t];
    float extra = yv + (z ? 0.f : bout[t]);
    rA = 0.5f * rA + extra;
    rB = 0.5f * rB + extra;
    if (z == 0) { g_RqA[(size_t)row * 64 + t] = rA; g_RqB[(size_t)row * 64 + t] = rB; }
    else        { g_CkA[(size_t)row * 64 + t] = rA; g_CkB[(size_t)row * 64 + t] = rB; }
}

// ---------------- 6) fused dot + epilogue ----------------
// Block: 32(q) x 32(k) tile for one b. dots held in regs for all 16 heads,
// then Wout applied + Rq/Ck added, output streamed directly. No g_dot scratch.
__global__ __launch_bounds__(256) void k_dotepi(const float* __restrict__ Wout,
                                                float* __restrict__ out) {
    __shared__ float Qs[32][68];
    __shared__ float Ks[32][68];
    __shared__ float Wt[16][68];
    int b  = blockIdx.z;
    int q0 = blockIdx.y * 32;
    int k0 = blockIdx.x * 32;
    int tid = threadIdx.x;
    int tx = tid & 15, ty = tid >> 4;

    for (int i = tid; i < 1024; i += 256)
        Wt[i & 15][i >> 4] = Wout[(i >> 4) * 16 + (i & 15)];  // Wt[h][d]

    float dt[4][16];
#pragma unroll
    for (int p = 0; p < 4; p++)
#pragma unroll
        for (int h = 0; h < 16; h++) dt[p][h] = 0.f;

    int lr = tid >> 3;           // 0..31
    int lc = (tid & 7) * 8;      // 0..56
    const float* qg = g_q + ((size_t)(b * PQ + q0 + lr)) * DIMD + lc;
    const float* kg = g_k + ((size_t)(b * PQ + k0 + lr)) * DIMD + lc;
    int ty2 = ty * 2, tx2 = tx * 2;

#pragma unroll
    for (int h = 0; h < 16; h++) {
        float4 qv0 = *(const float4*)(qg + h * 64);
        float4 qv1 = *(const float4*)(qg + h * 64 + 4);
        float4 kv0 = *(const float4*)(kg + h * 64);
        float4 kv1 = *(const float4*)(kg + h * 64 + 4);
        __syncthreads();
        *(float4*)&Qs[lr][lc]     = qv0;
        *(float4*)&Qs[lr][lc + 4] = qv1;
        *(float4*)&Ks[lr][lc]     = kv0;
        *(float4*)&Ks[lr][lc + 4] = kv1;
        __syncthreads();
#pragma unroll
        for (int c = 0; c < 64; c += 4) {
            float4 a0 = *(const float4*)&Qs[ty2][c];
            float4 a1 = *(const float4*)&Qs[ty2 + 1][c];
            float4 b0 = *(const float4*)&Ks[tx2][c];
            float4 b1 = *(const float4*)&Ks[tx2 + 1][c];
            dt[0][h] += (a0.x * b0.x + a0.y * b0.y) + (a0.z * b0.z + a0.w * b0.w);
            dt[1][h] += (a0.x * b1.x + a0.y * b1.y) + (a0.z * b1.z + a0.w * b1.w);
            dt[2][h] += (a1.x * b0.x + a1.y * b0.y) + (a1.z * b0.z + a1.w * b0.w);
            dt[3][h] += (a1.x * b1.x + a1.y * b1.y) + (a1.z * b1.z + a1.w * b1.w);
        }
    }

    // epilogue: out[b,q,k,:] = sum_h dt*Wout[:,h] + Rq(sel k) + Ck(sel q)
    const float* rqp[4];
    const float* ckp[4];
    float*       obp[4];
#pragma unroll
    for (int p = 0; p < 4; p++) {
        int q = q0 + ty2 + (p >> 1);
        int k = k0 + tx2 + (p & 1);
        rqp[p] = (k == PQ - 1 ? g_RqB : g_RqA) + ((size_t)(b * PQ + q)) * 64;
        ckp[p] = (q == PQ - 1 ? g_CkB : g_CkA) + ((size_t)(b * PQ + k)) * 64;
        obp[p] = out + (((size_t)(b * PQ + q) * PQ) + k) * 64;
    }
#pragma unroll
    for (int d4 = 0; d4 < 16; d4++) {
        float4 acc0 = make_float4(0, 0, 0, 0);
        float4 acc1 = make_float4(0, 0, 0, 0);
        float4 acc2 = make_float4(0, 0, 0, 0);
        float4 acc3 = make_float4(0, 0, 0, 0);
#pragma unroll
        for (int h = 0; h < 16; h++) {
            float4 w = *(const float4*)&Wt[h][d4 * 4];
            float v0 = dt[0][h], v1 = dt[1][h], v2 = dt[2][h], v3 = dt[3][h];
            acc0.x += v0 * w.x; acc0.y += v0 * w.y; acc0.z += v0 * w.z; acc0.w += v0 * w.w;
            acc1.x += v1 * w.x; acc1.y += v1 * w.y; acc1.z += v1 * w.z; acc1.w += v1 * w.w;
            acc2.x += v2 * w.x; acc2.y += v2 * w.y; acc2.z += v2 * w.z; acc2.w += v2 * w.w;
            acc3.x += v3 * w.x; acc3.y += v3 * w.y; acc3.z += v3 * w.z; acc3.w += v3 * w.w;
        }
        float4 av[4] = {acc0, acc1, acc2, acc3};
#pragma unroll
        for (int p = 0; p < 4; p++) {
            float4 rv = *(const float4*)(rqp[p] + d4 * 4);
            float4 cv = *(const float4*)(ckp[p] + d4 * 4);
            float4 o;
            o.x = av[p].x + rv.x + cv.x;
            o.y = av[p].y + rv.y + cv.y;
            o.z = av[p].z + rv.z + cv.z;
            o.w = av[p].w + rv.w + cv.w;
            *(float4*)(obp[p] + d4 * 4) = o;
        }
    }
}

extern "C" void kernel_launch(void* const* d_in, const int* in_sizes, int n_in,
                              void* d_out, int out_size) {
    const float* x    = (const float*)d_in[0];
    const float* Wq   = (const float*)d_in[1];
    const float* Wk   = (const float*)d_in[2];
    const float* Wpos = (const float*)d_in[3];
    const float* bpos = (const float*)d_in[4];
    const float* qb   = (const float*)d_in[5];
    const float* kb   = (const float*)d_in[6];
    const float* Wout = (const float*)d_in[7];
    const float* bout = (const float*)d_in[8];
    const float* Wyq  = (const float*)d_in[9];
    const float* Wyk  = (const float*)d_in[10];
    float* out = (float*)d_out;
    (void)in_sizes; (void)n_in; (void)out_size;

    k_pool   <<<2048, 256>>>(x);
    k_posenc <<<4, 256>>>(Wpos, bpos);
    k_proj   <<<dim3(8, 16, 2), 256>>>(Wq, Wk);
    k_y      <<<dim3(8, 16), 256>>>(Wyq, Wyk);
    k_scalars<<<dim3(2048, 2), 64>>>(qb, kb, Wout, bout);
    k_dotepi <<<dim3(16, 16, 4), 256>>>(Wout, out);
}

// round 5
// speedup vs baseline: 1.4905x; 1.4905x over previous
#include <cuda_runtime.h>
#include <cuda_bf16.h>
#include <mma.h>
#include <math.h>
#include <stdint.h>

using namespace nvcuda;

#define NB   4
#define DIMD 1024
#define PQ   512
#define NH   16
#define PD   64

// ---- static device scratch ----
static __device__ float g_xds  [NB * PQ * DIMD];
static __device__ float g_q    [NB * PQ * DIMD];
static __device__ float g_k    [NB * PQ * DIMD];
static __device__ float g_pA   [DIMD];
static __device__ float g_pB   [DIMD];
static __device__ float g_ypart[8 * 2048 * 128];
static __device__ float g_RqA  [NB * PQ * PD];
static __device__ float g_RqB  [NB * PQ * PD];
static __device__ float g_CkA  [NB * PQ * PD];
static __device__ float g_CkB  [NB * PQ * PD];
static __device__ float g_dot  [(size_t)NB * NH * PQ * PQ];   // 64 MB
// bf16 hi/lo splits
static __device__ __nv_bfloat16 g_xhi [2048 * 1024];
static __device__ __nv_bfloat16 g_xlo [2048 * 1024];
static __device__ __nv_bfloat16 g_wqhi[1024 * 1024];
static __device__ __nv_bfloat16 g_wqlo[1024 * 1024];
static __device__ __nv_bfloat16 g_wkhi[1024 * 1024];
static __device__ __nv_bfloat16 g_wklo[1024 * 1024];
static __device__ __nv_bfloat16 g_qhi [2048 * 1024];
static __device__ __nv_bfloat16 g_qlo [2048 * 1024];
static __device__ __nv_bfloat16 g_khi [2048 * 1024];
static __device__ __nv_bfloat16 g_klo [2048 * 1024];

// ---------------- 1) avg-pool (POOL=4) ----------------
__global__ void k_pool(const float* __restrict__ x) {
    int gid = blockIdx.x * blockDim.x + threadIdx.x;
    int d4 = gid & 255;
    int bp = gid >> 8;
    const float4* xin = reinterpret_cast<const float4*>(x);
    size_t base = (size_t)bp * 4 * 256 + d4;
    float4 r0 = xin[base], r1 = xin[base + 256], r2 = xin[base + 512], r3 = xin[base + 768];
    float4 o;
    o.x = (r0.x + r1.x + r2.x + r3.x) * 0.25f;
    o.y = (r0.y + r1.y + r2.y + r3.y) * 0.25f;
    o.z = (r0.z + r1.z + r2.z + r3.z) * 0.25f;
    o.w = (r0.w + r1.w + r2.w + r3.w) * 0.25f;
    reinterpret_cast<float4*>(g_xds)[(size_t)bp * 256 + d4] = o;
}

// ---------------- 2) pos_enc collapse ----------------
__global__ void k_posenc(const float* __restrict__ Wpos, const float* __restrict__ bpos) {
    int hc = blockIdx.x * blockDim.x + threadIdx.x;
    if (hc >= DIMD) return;
    float s1 = 0.f, s2 = 0.f;
#pragma unroll
    for (int j = 0; j < 32; j++) s1 += Wpos[hc * 64 + j];
#pragma unroll
    for (int j = 32; j < 64; j++) s2 += Wpos[hc * 64 + j];
    g_pA[hc] = s1 - s2 + bpos[hc];
    g_pB[hc] = s1 + bpos[hc];
}

// ---------------- bf16 hi/lo split helpers ----------------
__device__ __forceinline__ void split_store(const float4& v, __nv_bfloat16* hi,
                                            __nv_bfloat16* lo, size_t idx4) {
    float a[4] = {v.x, v.y, v.z, v.w};
    __nv_bfloat16 h[4], l[4];
#pragma unroll
    for (int e = 0; e < 4; e++) {
        h[e] = __float2bfloat16(a[e]);
        l[e] = __float2bfloat16(a[e] - __bfloat162float(h[e]));
    }
    *(uint2*)(hi + idx4 * 4) = *(uint2*)h;
    *(uint2*)(lo + idx4 * 4) = *(uint2*)l;
}

// split x_ds / Wq / Wk (pre-proj)
__global__ void k_split1(const float* __restrict__ Wq, const float* __restrict__ Wk) {
    int z = blockIdx.z;
    int gid = blockIdx.x * blockDim.x + threadIdx.x;   // float4 index
    int limit = (z == 0) ? (2048 * 256) : (1024 * 256);
    if (gid >= limit) return;
    const float4* src = reinterpret_cast<const float4*>(z == 0 ? g_xds : (z == 1 ? Wq : Wk));
    __nv_bfloat16* hi = z == 0 ? g_xhi : (z == 1 ? g_wqhi : g_wkhi);
    __nv_bfloat16* lo = z == 0 ? g_xlo : (z == 1 ? g_wqlo : g_wklo);
    split_store(src[gid], hi, lo, gid);
}

// split q / k (post-proj)
__global__ void k_split2() {
    int z = blockIdx.z;
    int gid = blockIdx.x * blockDim.x + threadIdx.x;   // 2048*256
    const float4* src = reinterpret_cast<const float4*>(z == 0 ? g_q : g_k);
    __nv_bfloat16* hi = z == 0 ? g_qhi : g_khi;
    __nv_bfloat16* lo = z == 0 ? g_qlo : g_klo;
    split_store(src[gid], hi, lo, gid);
}

// ---------------- 3) projection GEMM via wmma bf16 3-term split ----------------
// C[2048 x 1024] = Xsplit @ Wsplit^T. CTA tile 128x128, K-chunk 64.
#define RS 144                  // smem row stride bytes (72 bf16)
#define AH_OFF 0
#define AL_OFF (128 * RS)
#define BH_OFF (2 * 128 * RS)
#define BL_OFF (3 * 128 * RS)
#define GEMM_SMEM (4 * 128 * RS)

__global__ __launch_bounds__(256) void k_projmma() {
    extern __shared__ char smem[];
    int tid = threadIdx.x;
    int wid = tid >> 5;
    int m0 = blockIdx.y * 128;
    int n0 = blockIdx.x * 128;
    const __nv_bfloat16* Bhi = blockIdx.z ? g_wkhi : g_wqhi;
    const __nv_bfloat16* Blo = blockIdx.z ? g_wklo : g_wqlo;
    float* C = blockIdx.z ? g_k : g_q;

    int wm = wid & 3;        // 4 strips of 32 rows
    int wn = wid >> 2;       // 2 strips of 64 cols

    wmma::fragment<wmma::accumulator, 16, 16, 16, float> acc[2][4];
#pragma unroll
    for (int i = 0; i < 2; i++)
#pragma unroll
        for (int j = 0; j < 4; j++) wmma::fill_fragment(acc[i][j], 0.f);

    for (int k0 = 0; k0 < 1024; k0 += 64) {
        __syncthreads();
#pragma unroll
        for (int i = 0; i < 4; i++) {
            int l = i * 256 + tid;
            int r = l >> 3, f = l & 7;
            size_t goff = (size_t)(m0 + r) * 1024 + k0 + f * 8;
            *(float4*)(smem + AH_OFF + r * RS + f * 16) = *(const float4*)(g_xhi + goff);
            *(float4*)(smem + AL_OFF + r * RS + f * 16) = *(const float4*)(g_xlo + goff);
            size_t boff = (size_t)(n0 + r) * 1024 + k0 + f * 8;
            *(float4*)(smem + BH_OFF + r * RS + f * 16) = *(const float4*)(Bhi + boff);
            *(float4*)(smem + BL_OFF + r * RS + f * 16) = *(const float4*)(Blo + boff);
        }
        __syncthreads();
        const __nv_bfloat16* pAh = (const __nv_bfloat16*)(smem + AH_OFF);
        const __nv_bfloat16* pAl = (const __nv_bfloat16*)(smem + AL_OFF);
        const __nv_bfloat16* pBh = (const __nv_bfloat16*)(smem + BH_OFF);
        const __nv_bfloat16* pBl = (const __nv_bfloat16*)(smem + BL_OFF);
#pragma unroll
        for (int ks = 0; ks < 4; ks++) {
            wmma::fragment<wmma::matrix_a, 16, 16, 16, __nv_bfloat16, wmma::row_major> ah[2], al[2];
            wmma::fragment<wmma::matrix_b, 16, 16, 16, __nv_bfloat16, wmma::col_major> bh[4], bl[4];
#pragma unroll
            for (int i = 0; i < 2; i++) {
                int mrow = wm * 32 + i * 16;
                wmma::load_matrix_sync(ah[i], pAh + mrow * 72 + ks * 16, 72);
                wmma::load_matrix_sync(al[i], pAl + mrow * 72 + ks * 16, 72);
            }
#pragma unroll
            for (int j = 0; j < 4; j++) {
                int nrow = wn * 64 + j * 16;
                wmma::load_matrix_sync(bh[j], pBh + nrow * 72 + ks * 16, 72);
                wmma::load_matrix_sync(bl[j], pBl + nrow * 72 + ks * 16, 72);
            }
#pragma unroll
            for (int i = 0; i < 2; i++)
#pragma unroll
                for (int j = 0; j < 4; j++) {
                    wmma::mma_sync(acc[i][j], ah[i], bh[j], acc[i][j]);
                    wmma::mma_sync(acc[i][j], ah[i], bl[j], acc[i][j]);
                    wmma::mma_sync(acc[i][j], al[i], bh[j], acc[i][j]);
                }
        }
    }
#pragma unroll
    for (int i = 0; i < 2; i++)
#pragma unroll
        for (int j = 0; j < 4; j++) {
            float* p = C + (size_t)(m0 + wm * 32 + i * 16) * 1024 + n0 + wn * 64 + j * 16;
            wmma::store_matrix_sync(p, acc[i][j], 1024, wmma::mem_row_major);
        }
}

// ---------------- 4) y partials (K split 8 ways, SIMT) ----------------
__global__ __launch_bounds__(256) void k_y(const float* __restrict__ Wyq,
                                           const float* __restrict__ Wyk) {
    __shared__ float As[16][132];
    __shared__ float Bs[16][132];
    int ks = blockIdx.x;
    int bm = blockIdx.y * 128;
    int tid = threadIdx.x;
    int lr = tid >> 1;
    int lc = (tid & 1) * 8;
    int tx = tid & 15;
    int ty = tid >> 4;
    float acc[8][8];
#pragma unroll
    for (int i = 0; i < 8; i++)
#pragma unroll
        for (int j = 0; j < 8; j++) acc[i][j] = 0.f;

    const float* aptr = g_xds + (size_t)(bm + lr) * DIMD + ks * 128 + lc;
    const float* brow = (lr < 64) ? (Wyq + (size_t)lr * DIMD) : (Wyk + (size_t)(lr - 64) * DIMD);
    const float* bptr = brow + ks * 128 + lc;

    for (int k0 = 0; k0 < 128; k0 += 16) {
        float4 a0 = *(const float4*)(aptr + k0);
        float4 a1 = *(const float4*)(aptr + k0 + 4);
        float4 b0 = *(const float4*)(bptr + k0);
        float4 b1 = *(const float4*)(bptr + k0 + 4);
        float av8[8] = {a0.x, a0.y, a0.z, a0.w, a1.x, a1.y, a1.z, a1.w};
#pragma unroll
        for (int e = 0; e < 8; e++)
            av8[e] = 0.5f * av8[e] * (1.f + erff(av8[e] * 0.70710678118654752f));
        __syncthreads();
#pragma unroll
        for (int e = 0; e < 8; e++) As[lc + e][lr] = av8[e];
        Bs[lc + 0][lr] = b0.x; Bs[lc + 1][lr] = b0.y;
        Bs[lc + 2][lr] = b0.z; Bs[lc + 3][lr] = b0.w;
        Bs[lc + 4][lr] = b1.x; Bs[lc + 5][lr] = b1.y;
        Bs[lc + 6][lr] = b1.z; Bs[lc + 7][lr] = b1.w;
        __syncthreads();
#pragma unroll
        for (int kk = 0; kk < 16; kk++) {
            float4 af0 = *(const float4*)&As[kk][ty * 4];
            float4 af1 = *(const float4*)&As[kk][64 + ty * 4];
            float4 bf0 = *(const float4*)&Bs[kk][tx * 4];
            float4 bf1 = *(const float4*)&Bs[kk][64 + tx * 4];
            float av[8] = {af0.x, af0.y, af0.z, af0.w, af1.x, af1.y, af1.z, af1.w};
            float bv[8] = {bf0.x, bf0.y, bf0.z, bf0.w, bf1.x, bf1.y, bf1.z, bf1.w};
#pragma unroll
            for (int i = 0; i < 8; i++)
#pragma unroll
                for (int j = 0; j < 8; j++) acc[i][j] += av[i] * bv[j];
        }
    }
#pragma unroll
    for (int i = 0; i < 8; i++) {
        int r = bm + (i < 4 ? ty * 4 + i : 64 + ty * 4 + (i - 4));
        float4 v0 = make_float4(acc[i][0], acc[i][1], acc[i][2], acc[i][3]);
        float4 v1 = make_float4(acc[i][4], acc[i][5], acc[i][6], acc[i][7]);
        *(float4*)&g_ypart[((size_t)ks * 2048 + r) * 128 + tx * 4]      = v0;
        *(float4*)&g_ypart[((size_t)ks * 2048 + r) * 128 + 64 + tx * 4] = v1;
    }
}

// ---------------- 5) row/col correction tensors ----------------
__global__ __launch_bounds__(64) void k_scalars(const float* __restrict__ qbias,
                                                const float* __restrict__ kbias,
                                                const float* __restrict__ Wout,
                                                const float* __restrict__ bout) {
    __shared__ float sA[16], sB[16];
    int row = blockIdx.x;
    int z = blockIdx.y;
    const float* src  = z ? g_k : g_q;
    const float* bias = z ? kbias : qbias;
    int t = threadIdx.x;
    if (t < 16) {
        float a = 0.f, bs = 0.f;
        int base = t * 64;
        for (int c = 0; c < 64; c++) {
            float v = src[(size_t)row * DIMD + base + c] + bias[base + c];
            a  += v * g_pA[base + c];
            bs += v * g_pB[base + c];
        }
        sA[t] = a; sB[t] = bs;
    }
    __syncthreads();
    float rA = 0.f, rB = 0.f;
#pragma unroll
    for (int h = 0; h < 16; h++) {
        float w = Wout[t * 16 + h];
        rA += sA[h] * w;
        rB += sB[h] * w;
    }
    float yv = 0.f;
#pragma unroll
    for (int s = 0; s < 8; s++)
        yv += g_ypart[((size_t)s * 2048 + row) * 128 + z * 64 + t];
    float extra = yv + (z ? 0.f : bout[t]);
    rA = 0.5f * rA + extra;
    rB = 0.5f * rB + extra;
    if (z == 0) { g_RqA[(size_t)row * 64 + t] = rA; g_RqB[(size_t)row * 64 + t] = rB; }
    else        { g_CkA[(size_t)row * 64 + t] = rA; g_CkB[(size_t)row * 64 + t] = rB; }
}

// ---------------- 6) dot GEMM per (b,h) via wmma: 512x512x64 ----------------
__global__ __launch_bounds__(256) void k_dot() {
    extern __shared__ char smem[];
    int bh = blockIdx.z;
    int b = bh >> 4, h = bh & 15;
    int q0 = blockIdx.y * 128;
    int n0 = blockIdx.x * 128;   // k index
    int tid = threadIdx.x;
    int wid = tid >> 5;
    int wm = wid & 3;
    int wn = wid >> 2;

#pragma unroll
    for (int i = 0; i < 4; i++) {
        int l = i * 256 + tid;
        int r = l >> 3, f = l & 7;
        size_t qoff = ((size_t)(b * PQ + q0 + r)) * 1024 + h * 64 + f * 8;
        size_t koff = ((size_t)(b * PQ + n0 + r)) * 1024 + h * 64 + f * 8;
        *(float4*)(smem + AH_OFF + r * RS + f * 16) = *(const float4*)(g_qhi + qoff);
        *(float4*)(smem + AL_OFF + r * RS + f * 16) = *(const float4*)(g_qlo + qoff);
        *(float4*)(smem + BH_OFF + r * RS + f * 16) = *(const float4*)(g_khi + koff);
        *(float4*)(smem + BL_OFF + r * RS + f * 16) = *(const float4*)(g_klo + koff);
    }
    __syncthreads();

    wmma::fragment<wmma::accumulator, 16, 16, 16, float> acc[2][4];
#pragma unroll
    for (int i = 0; i < 2; i++)
#pragma unroll
        for (int j = 0; j < 4; j++) wmma::fill_fragment(acc[i][j], 0.f);

    const __nv_bfloat16* pAh = (const __nv_bfloat16*)(smem + AH_OFF);
    const __nv_bfloat16* pAl = (const __nv_bfloat16*)(smem + AL_OFF);
    const __nv_bfloat16* pBh = (const __nv_bfloat16*)(smem + BH_OFF);
    const __nv_bfloat16* pBl = (const __nv_bfloat16*)(smem + BL_OFF);
#pragma unroll
    for (int ks = 0; ks < 4; ks++) {
        wmma::fragment<wmma::matrix_a, 16, 16, 16, __nv_bfloat16, wmma::row_major> ah[2], al[2];
        wmma::fragment<wmma::matrix_b, 16, 16, 16, __nv_bfloat16, wmma::col_major> bh[4], bl[4];
#pragma unroll
        for (int i = 0; i < 2; i++) {
            int mrow = wm * 32 + i * 16;
            wmma::load_matrix_sync(ah[i], pAh + mrow * 72 + ks * 16, 72);
            wmma::load_matrix_sync(al[i], pAl + mrow * 72 + ks * 16, 72);
        }
#pragma unroll
        for (int j = 0; j < 4; j++) {
            int nrow = wn * 64 + j * 16;
            wmma::load_matrix_sync(bh[j], pBh + nrow * 72 + ks * 16, 72);
            wmma::load_matrix_sync(bl[j], pBl + nrow * 72 + ks * 16, 72);
        }
#pragma unroll
        for (int i = 0; i < 2; i++)
#pragma unroll
            for (int j = 0; j < 4; j++) {
                wmma::mma_sync(acc[i][j], ah[i], bh[j], acc[i][j]);
                wmma::mma_sync(acc[i][j], ah[i], bl[j], acc[i][j]);
                wmma::mma_sync(acc[i][j], al[i], bh[j], acc[i][j]);
            }
    }
    float* outb = g_dot + ((size_t)(b * NH + h) * PQ) * PQ;
#pragma unroll
    for (int i = 0; i < 2; i++)
#pragma unroll
        for (int j = 0; j < 4; j++) {
            float* p = outb + (size_t)(q0 + wm * 32 + i * 16) * PQ + n0 + wn * 64 + j * 16;
            wmma::store_matrix_sync(p, acc[i][j], PQ, wmma::mem_row_major);
        }
}

// ---------------- 7) epilogue (R2 version) ----------------
__global__ __launch_bounds__(256) void k_epilogue(const float* __restrict__ Wout,
                                                  float* __restrict__ out) {
    __shared__ float As[16][512];
    int q = blockIdx.x;
    int b = blockIdx.y;
    int tid = threadIdx.x;
#pragma unroll
    for (int it = 0; it < 8; it++) {
        int idx = it * 256 + tid;
        int h = idx >> 7, k4 = idx & 127;
        float4 v = *(const float4*)(g_dot + ((size_t)(b * NH + h) * PQ + q) * PQ + k4 * 4);
        *(float4*)&As[h][k4 * 4] = v;
    }
    __syncthreads();
    int dp = tid & 31;
    int kk = tid >> 5;
    int d0 = dp, d1 = dp + 32;
    float w0[16], w1[16];
#pragma unroll
    for (int h = 0; h < 16; h++) {
        w0[h] = Wout[d0 * 16 + h];
        w1[h] = Wout[d1 * 16 + h];
    }
    size_t rowq = (size_t)b * PQ + q;
    float rqA0 = g_RqA[rowq * 64 + d0], rqA1 = g_RqA[rowq * 64 + d1];
    float rqB0 = g_RqB[rowq * 64 + d0], rqB1 = g_RqB[rowq * 64 + d1];
    const float* ck = (q == PQ - 1 ? g_CkB : g_CkA) + (size_t)b * PQ * 64;
    float* obase = out + rowq * PQ * 64;
    for (int it = 0; it < 64; it++) {
        int k = it * 8 + kk;
        float a0 = 0.f, a1 = 0.f;
#pragma unroll
        for (int h = 0; h < 16; h++) {
            float av = As[h][k];
            a0 += av * w0[h];
            a1 += av * w1[h];
        }
        float rq0 = (k == PQ - 1) ? rqB0 : rqA0;
        float rq1 = (k == PQ - 1) ? rqB1 : rqA1;
        obase[(size_t)k * 64 + d0] = a0 + rq0 + ck[(size_t)k * 64 + d0];
        obase[(size_t)k * 64 + d1] = a1 + rq1 + ck[(size_t)k * 64 + d1];
    }
}

extern "C" void kernel_launch(void* const* d_in, const int* in_sizes, int n_in,
                              void* d_out, int out_size) {
    const float* x    = (const float*)d_in[0];
    const float* Wq   = (const float*)d_in[1];
    const float* Wk   = (const float*)d_in[2];
    const float* Wpos = (const float*)d_in[3];
    const float* bpos = (const float*)d_in[4];
    const float* qb   = (const float*)d_in[5];
    const float* kb   = (const float*)d_in[6];
    const float* Wout = (const float*)d_in[7];
    const float* bout = (const float*)d_in[8];
    const float* Wyq  = (const float*)d_in[9];
    const float* Wyk  = (const float*)d_in[10];
    float* out = (float*)d_out;
    (void)in_sizes; (void)n_in; (void)out_size;

    static int smem_set = 0;
    if (!smem_set) {
        cudaFuncSetAttribute(k_projmma, cudaFuncAttributeMaxDynamicSharedMemorySize, GEMM_SMEM);
        cudaFuncSetAttribute(k_dot,     cudaFuncAttributeMaxDynamicSharedMemorySize, GEMM_SMEM);
        smem_set = 1;
    }

    k_pool   <<<2048, 256>>>(x);
    k_posenc <<<4, 256>>>(Wpos, bpos);
    k_split1 <<<dim3(2048, 1, 3), 256>>>(Wq, Wk);
    k_projmma<<<dim3(8, 16, 2), 256, GEMM_SMEM>>>();
    k_split2 <<<dim3(2048, 1, 2), 256>>>();
    k_y      <<<dim3(8, 16), 256>>>(Wyq, Wyk);
    k_scalars<<<dim3(2048, 2), 64>>>(qb, kb, Wout, bout);
    k_dot    <<<dim3(4, 4, 64), 256, GEMM_SMEM>>>();
    k_epilogue<<<dim3(512, 4), 256>>>(Wout, out);
}

// round 6
// speedup vs baseline: 1.6428x; 1.1022x over previous
#include <cuda_runtime.h>
#include <cuda_bf16.h>
#include <mma.h>
#include <math.h>
#include <stdint.h>

using namespace nvcuda;

#define NB   4
#define DIMD 1024
#define PQ   512
#define NH   16
#define PD   64

// ---- static device scratch ----
static __device__ float g_xds  [NB * PQ * DIMD];
static __device__ float g_pA   [DIMD];
static __device__ float g_pB   [DIMD];
static __device__ float g_ypart[8 * 2048 * 128];
static __device__ float g_RqA  [NB * PQ * PD];
static __device__ float g_RqB  [NB * PQ * PD];
static __device__ float g_CkA  [NB * PQ * PD];
static __device__ float g_CkB  [NB * PQ * PD];
static __device__ float g_dot  [(size_t)NB * NH * PQ * PQ];   // 64 MB
// bf16 hi/lo splits
static __device__ __nv_bfloat16 g_xhi [2048 * 1024];
static __device__ __nv_bfloat16 g_xlo [2048 * 1024];
static __device__ __nv_bfloat16 g_wqhi[1024 * 1024];
static __device__ __nv_bfloat16 g_wqlo[1024 * 1024];
static __device__ __nv_bfloat16 g_wkhi[1024 * 1024];
static __device__ __nv_bfloat16 g_wklo[1024 * 1024];
static __device__ __nv_bfloat16 g_qhi [2048 * 1024];
static __device__ __nv_bfloat16 g_qlo [2048 * 1024];
static __device__ __nv_bfloat16 g_khi [2048 * 1024];
static __device__ __nv_bfloat16 g_klo [2048 * 1024];

// ---- cp.async helpers ----
#define CP_ASYNC16(dst, src) \
    asm volatile("cp.async.cg.shared.global [%0], [%1], 16;" :: "r"(dst), "l"(src))
#define CP_COMMIT() asm volatile("cp.async.commit_group;")
#define CP_WAIT(n)  asm volatile("cp.async.wait_group %0;" :: "n"(n))

// ---------------- 1) avg-pool (POOL=4) ----------------
__global__ void k_pool(const float* __restrict__ x) {
    int gid = blockIdx.x * blockDim.x + threadIdx.x;
    int d4 = gid & 255;
    int bp = gid >> 8;
    const float4* xin = reinterpret_cast<const float4*>(x);
    size_t base = (size_t)bp * 4 * 256 + d4;
    float4 r0 = xin[base], r1 = xin[base + 256], r2 = xin[base + 512], r3 = xin[base + 768];
    float4 o;
    o.x = (r0.x + r1.x + r2.x + r3.x) * 0.25f;
    o.y = (r0.y + r1.y + r2.y + r3.y) * 0.25f;
    o.z = (r0.z + r1.z + r2.z + r3.z) * 0.25f;
    o.w = (r0.w + r1.w + r2.w + r3.w) * 0.25f;
    reinterpret_cast<float4*>(g_xds)[(size_t)bp * 256 + d4] = o;
}

// ---------------- 2) pos_enc collapse ----------------
__global__ void k_posenc(const float* __restrict__ Wpos, const float* __restrict__ bpos) {
    int hc = blockIdx.x * blockDim.x + threadIdx.x;
    if (hc >= DIMD) return;
    float s1 = 0.f, s2 = 0.f;
#pragma unroll
    for (int j = 0; j < 32; j++) s1 += Wpos[hc * 64 + j];
#pragma unroll
    for (int j = 32; j < 64; j++) s2 += Wpos[hc * 64 + j];
    g_pA[hc] = s1 - s2 + bpos[hc];
    g_pB[hc] = s1 + bpos[hc];
}

// ---------------- bf16 hi/lo split ----------------
__device__ __forceinline__ void split_store(const float4& v, __nv_bfloat16* hi,
                                            __nv_bfloat16* lo, size_t idx4) {
    float a[4] = {v.x, v.y, v.z, v.w};
    __nv_bfloat16 h[4], l[4];
#pragma unroll
    for (int e = 0; e < 4; e++) {
        h[e] = __float2bfloat16(a[e]);
        l[e] = __float2bfloat16(a[e] - __bfloat162float(h[e]));
    }
    *(uint2*)(hi + idx4 * 4) = *(uint2*)h;
    *(uint2*)(lo + idx4 * 4) = *(uint2*)l;
}

__global__ void k_split1(const float* __restrict__ Wq, const float* __restrict__ Wk) {
    int z = blockIdx.z;
    int gid = blockIdx.x * blockDim.x + threadIdx.x;
    int limit = (z == 0) ? (2048 * 256) : (1024 * 256);
    if (gid >= limit) return;
    const float4* src = reinterpret_cast<const float4*>(z == 0 ? g_xds : (z == 1 ? Wq : Wk));
    __nv_bfloat16* hi = z == 0 ? g_xhi : (z == 1 ? g_wqhi : g_wkhi);
    __nv_bfloat16* lo = z == 0 ? g_xlo : (z == 1 ? g_wqlo : g_wklo);
    split_store(src[gid], hi, lo, gid);
}

// ---------------- 3) projection GEMM: wmma + cp.async double buffer ----------------
#define RS 144                   // smem row stride bytes (72 bf16)
#define TILE_BYTES (128 * RS)    // 18432
#define STG_A_H(s) ((s) * 4 * TILE_BYTES + 0 * TILE_BYTES)
#define STG_A_L(s) ((s) * 4 * TILE_BYTES + 1 * TILE_BYTES)
#define STG_B_H(s) ((s) * 4 * TILE_BYTES + 2 * TILE_BYTES)
#define STG_B_L(s) ((s) * 4 * TILE_BYTES + 3 * TILE_BYTES)
#define GEMM_SMEM (2 * 4 * TILE_BYTES)   // 147456

__global__ __launch_bounds__(256) void k_projmma() {
    extern __shared__ char smem[];
    int tid = threadIdx.x;
    int wid = tid >> 5;
    int m0 = blockIdx.y * 128;
    int n0 = blockIdx.x * 128;
    const __nv_bfloat16* Bhi = blockIdx.z ? g_wkhi : g_wqhi;
    const __nv_bfloat16* Blo = blockIdx.z ? g_wklo : g_wqlo;
    __nv_bfloat16* Chi = blockIdx.z ? g_khi : g_qhi;
    __nv_bfloat16* Clo = blockIdx.z ? g_klo : g_qlo;

    int wm = wid & 3;
    int wn = wid >> 2;
    uint32_t sbase = (uint32_t)__cvta_generic_to_shared(smem);

    int lr = tid >> 1;           // 0..127 row
    int lf = (tid & 1) * 4;      // 0 or 4 (16B chunks, 8 per 128B row)

    wmma::fragment<wmma::accumulator, 16, 16, 16, float> acc[2][4];
#pragma unroll
    for (int i = 0; i < 2; i++)
#pragma unroll
        for (int j = 0; j < 4; j++) wmma::fill_fragment(acc[i][j], 0.f);

    // async load of one K-chunk (64 cols) into stage s
    auto loadchunk = [&](int c, int s) {
        size_t ga = (size_t)(m0 + lr) * 1024 + c * 64;   // elements
        size_t gb = (size_t)(n0 + lr) * 1024 + c * 64;
#pragma unroll
        for (int f = 0; f < 4; f++) {
            int fo = lf + f;
            CP_ASYNC16(sbase + STG_A_H(s) + lr * RS + fo * 16, (const char*)(g_xhi + ga) + fo * 16);
            CP_ASYNC16(sbase + STG_A_L(s) + lr * RS + fo * 16, (const char*)(g_xlo + ga) + fo * 16);
            CP_ASYNC16(sbase + STG_B_H(s) + lr * RS + fo * 16, (const char*)(Bhi + gb) + fo * 16);
            CP_ASYNC16(sbase + STG_B_L(s) + lr * RS + fo * 16, (const char*)(Blo + gb) + fo * 16);
        }
    };

    loadchunk(0, 0);
    CP_COMMIT();

    for (int c = 0; c < 16; c++) {
        if (c < 15) {
            loadchunk(c + 1, (c + 1) & 1);
            CP_COMMIT();
            CP_WAIT(1);
        } else {
            CP_WAIT(0);
        }
        __syncthreads();
        int s = c & 1;
        const __nv_bfloat16* pAh = (const __nv_bfloat16*)(smem + STG_A_H(s));
        const __nv_bfloat16* pAl = (const __nv_bfloat16*)(smem + STG_A_L(s));
        const __nv_bfloat16* pBh = (const __nv_bfloat16*)(smem + STG_B_H(s));
        const __nv_bfloat16* pBl = (const __nv_bfloat16*)(smem + STG_B_L(s));
#pragma unroll
        for (int ks = 0; ks < 4; ks++) {
            wmma::fragment<wmma::matrix_a, 16, 16, 16, __nv_bfloat16, wmma::row_major> ah[2], al[2];
            wmma::fragment<wmma::matrix_b, 16, 16, 16, __nv_bfloat16, wmma::col_major> bh[4], bl[4];
#pragma unroll
            for (int i = 0; i < 2; i++) {
                int mrow = wm * 32 + i * 16;
                wmma::load_matrix_sync(ah[i], pAh + mrow * 72 + ks * 16, 72);
                wmma::load_matrix_sync(al[i], pAl + mrow * 72 + ks * 16, 72);
            }
#pragma unroll
            for (int j = 0; j < 4; j++) {
                int nrow = wn * 64 + j * 16;
                wmma::load_matrix_sync(bh[j], pBh + nrow * 72 + ks * 16, 72);
                wmma::load_matrix_sync(bl[j], pBl + nrow * 72 + ks * 16, 72);
            }
#pragma unroll
            for (int i = 0; i < 2; i++)
#pragma unroll
                for (int j = 0; j < 4; j++) {
                    wmma::mma_sync(acc[i][j], ah[i], bh[j], acc[i][j]);
                    wmma::mma_sync(acc[i][j], ah[i], bl[j], acc[i][j]);
                    wmma::mma_sync(acc[i][j], al[i], bh[j], acc[i][j]);
                }
        }
        __syncthreads();
    }

    // stage fp32 tile in smem, then split-store to hi/lo bf16
    float* Cs = (float*)smem;    // 128x128 f32 = 64KB
#pragma unroll
    for (int i = 0; i < 2; i++)
#pragma unroll
        for (int j = 0; j < 4; j++)
            wmma::store_matrix_sync(Cs + (wm * 32 + i * 16) * 128 + wn * 64 + j * 16,
                                    acc[i][j], 128, wmma::mem_row_major);
    __syncthreads();
#pragma unroll
    for (int it = 0; it < 16; it++) {
        int idx = it * 256 + tid;      // 4096 float4
        int r = idx >> 5, c4 = idx & 31;
        float4 v = reinterpret_cast<const float4*>(Cs)[idx];
        size_t off4 = ((size_t)(m0 + r) * 1024 + n0) / 4 + c4;
        split_store(v, Chi, Clo, off4);
    }
}

// ---------------- 4) y partials (K split 8 ways, SIMT) ----------------
__global__ __launch_bounds__(256) void k_y(const float* __restrict__ Wyq,
                                           const float* __restrict__ Wyk) {
    __shared__ float As[16][132];
    __shared__ float Bs[16][132];
    int ks = blockIdx.x;
    int bm = blockIdx.y * 128;
    int tid = threadIdx.x;
    int lr = tid >> 1;
    int lc = (tid & 1) * 8;
    int tx = tid & 15;
    int ty = tid >> 4;
    float acc[8][8];
#pragma unroll
    for (int i = 0; i < 8; i++)
#pragma unroll
        for (int j = 0; j < 8; j++) acc[i][j] = 0.f;

    const float* aptr = g_xds + (size_t)(bm + lr) * DIMD + ks * 128 + lc;
    const float* brow = (lr < 64) ? (Wyq + (size_t)lr * DIMD) : (Wyk + (size_t)(lr - 64) * DIMD);
    const float* bptr = brow + ks * 128 + lc;

    for (int k0 = 0; k0 < 128; k0 += 16) {
        float4 a0 = *(const float4*)(aptr + k0);
        float4 a1 = *(const float4*)(aptr + k0 + 4);
        float4 b0 = *(const float4*)(bptr + k0);
        float4 b1 = *(const float4*)(bptr + k0 + 4);
        float av8[8] = {a0.x, a0.y, a0.z, a0.w, a1.x, a1.y, a1.z, a1.w};
#pragma unroll
        for (int e = 0; e < 8; e++)
            av8[e] = 0.5f * av8[e] * (1.f + erff(av8[e] * 0.70710678118654752f));
        __syncthreads();
#pragma unroll
        for (int e = 0; e < 8; e++) As[lc + e][lr] = av8[e];
        Bs[lc + 0][lr] = b0.x; Bs[lc + 1][lr] = b0.y;
        Bs[lc + 2][lr] = b0.z; Bs[lc + 3][lr] = b0.w;
        Bs[lc + 4][lr] = b1.x; Bs[lc + 5][lr] = b1.y;
        Bs[lc + 6][lr] = b1.z; Bs[lc + 7][lr] = b1.w;
        __syncthreads();
#pragma unroll
        for (int kk = 0; kk < 16; kk++) {
            float4 af0 = *(const float4*)&As[kk][ty * 4];
            float4 af1 = *(const float4*)&As[kk][64 + ty * 4];
            float4 bf0 = *(const float4*)&Bs[kk][tx * 4];
            float4 bf1 = *(const float4*)&Bs[kk][64 + tx * 4];
            float av[8] = {af0.x, af0.y, af0.z, af0.w, af1.x, af1.y, af1.z, af1.w};
            float bv[8] = {bf0.x, bf0.y, bf0.z, bf0.w, bf1.x, bf1.y, bf1.z, bf1.w};
#pragma unroll
            for (int i = 0; i < 8; i++)
#pragma unroll
                for (int j = 0; j < 8; j++) acc[i][j] += av[i] * bv[j];
        }
    }
#pragma unroll
    for (int i = 0; i < 8; i++) {
        int r = bm + (i < 4 ? ty * 4 + i : 64 + ty * 4 + (i - 4));
        float4 v0 = make_float4(acc[i][0], acc[i][1], acc[i][2], acc[i][3]);
        float4 v1 = make_float4(acc[i][4], acc[i][5], acc[i][6], acc[i][7]);
        *(float4*)&g_ypart[((size_t)ks * 2048 + r) * 128 + tx * 4]      = v0;
        *(float4*)&g_ypart[((size_t)ks * 2048 + r) * 128 + 64 + tx * 4] = v1;
    }
}

// ---------------- 5) row/col correction tensors ----------------
__global__ __launch_bounds__(64) void k_scalars(const float* __restrict__ qbias,
                                                const float* __restrict__ kbias,
                                                const float* __restrict__ Wout,
                                                const float* __restrict__ bout) {
    __shared__ float sA[16], sB[16];
    int row = blockIdx.x;
    int z = blockIdx.y;
    const __nv_bfloat16* shi = z ? g_khi : g_qhi;
    const __nv_bfloat16* slo = z ? g_klo : g_qlo;
    const float* bias = z ? kbias : qbias;
    int t = threadIdx.x;
    if (t < 16) {
        float a = 0.f, bs = 0.f;
        int base = t * 64;
        for (int c = 0; c < 64; c++) {
            float v = __bfloat162float(shi[(size_t)row * DIMD + base + c])
                    + __bfloat162float(slo[(size_t)row * DIMD + base + c])
                    + bias[base + c];
            a  += v * g_pA[base + c];
            bs += v * g_pB[base + c];
        }
        sA[t] = a; sB[t] = bs;
    }
    __syncthreads();
    float rA = 0.f, rB = 0.f;
#pragma unroll
    for (int h = 0; h < 16; h++) {
        float w = Wout[t * 16 + h];
        rA += sA[h] * w;
        rB += sB[h] * w;
    }
    float yv = 0.f;
#pragma unroll
    for (int s = 0; s < 8; s++)
        yv += g_ypart[((size_t)s * 2048 + row) * 128 + z * 64 + t];
    float extra = yv + (z ? 0.f : bout[t]);
    rA = 0.5f * rA + extra;
    rB = 0.5f * rB + extra;
    if (z == 0) { g_RqA[(size_t)row * 64 + t] = rA; g_RqB[(size_t)row * 64 + t] = rB; }
    else        { g_CkA[(size_t)row * 64 + t] = rA; g_CkB[(size_t)row * 64 + t] = rB; }
}

// ---------------- 6) dot GEMM per (b,h) via wmma: 512x512x64 ----------------
#define DOT_SMEM (4 * TILE_BYTES)
__global__ __launch_bounds__(256) void k_dot() {
    extern __shared__ char smem[];
    int bh = blockIdx.z;
    int b = bh >> 4, h = bh & 15;
    int q0 = blockIdx.y * 128;
    int n0 = blockIdx.x * 128;
    int tid = threadIdx.x;
    int wid = tid >> 5;
    int wm = wid & 3;
    int wn = wid >> 2;

#pragma unroll
    for (int i = 0; i < 4; i++) {
        int l = i * 256 + tid;
        int r = l >> 3, f = l & 7;
        size_t qoff = ((size_t)(b * PQ + q0 + r)) * 1024 + h * 64 + f * 8;
        size_t koff = ((size_t)(b * PQ + n0 + r)) * 1024 + h * 64 + f * 8;
        *(float4*)(smem + 0 * TILE_BYTES + r * RS + f * 16) = *(const float4*)(g_qhi + qoff);
        *(float4*)(smem + 1 * TILE_BYTES + r * RS + f * 16) = *(const float4*)(g_qlo + qoff);
        *(float4*)(smem + 2 * TILE_BYTES + r * RS + f * 16) = *(const float4*)(g_khi + koff);
        *(float4*)(smem + 3 * TILE_BYTES + r * RS + f * 16) = *(const float4*)(g_klo + koff);
    }
    __syncthreads();

    wmma::fragment<wmma::accumulator, 16, 16, 16, float> acc[2][4];
#pragma unroll
    for (int i = 0; i < 2; i++)
#pragma unroll
        for (int j = 0; j < 4; j++) wmma::fill_fragment(acc[i][j], 0.f);

    const __nv_bfloat16* pAh = (const __nv_bfloat16*)(smem + 0 * TILE_BYTES);
    const __nv_bfloat16* pAl = (const __nv_bfloat16*)(smem + 1 * TILE_BYTES);
    const __nv_bfloat16* pBh = (const __nv_bfloat16*)(smem + 2 * TILE_BYTES);
    const __nv_bfloat16* pBl = (const __nv_bfloat16*)(smem + 3 * TILE_BYTES);
#pragma unroll
    for (int ks = 0; ks < 4; ks++) {
        wmma::fragment<wmma::matrix_a, 16, 16, 16, __nv_bfloat16, wmma::row_major> ah[2], al[2];
        wmma::fragment<wmma::matrix_b, 16, 16, 16, __nv_bfloat16, wmma::col_major> bh[4], bl[4];
#pragma unroll
        for (int i = 0; i < 2; i++) {
            int mrow = wm * 32 + i * 16;
            wmma::load_matrix_sync(ah[i], pAh + mrow * 72 + ks * 16, 72);
            wmma::load_matrix_sync(al[i], pAl + mrow * 72 + ks * 16, 72);
        }
#pragma unroll
        for (int j = 0; j < 4; j++) {
            int nrow = wn * 64 + j * 16;
            wmma::load_matrix_sync(bh[j], pBh + nrow * 72 + ks * 16, 72);
            wmma::load_matrix_sync(bl[j], pBl + nrow * 72 + ks * 16, 72);
        }
#pragma unroll
        for (int i = 0; i < 2; i++)
#pragma unroll
            for (int j = 0; j < 4; j++) {
                wmma::mma_sync(acc[i][j], ah[i], bh[j], acc[i][j]);
                wmma::mma_sync(acc[i][j], ah[i], bl[j], acc[i][j]);
                wmma::mma_sync(acc[i][j], al[i], bh[j], acc[i][j]);
            }
    }
    float* outb = g_dot + ((size_t)(b * NH + h) * PQ) * PQ;
#pragma unroll
    for (int i = 0; i < 2; i++)
#pragma unroll
        for (int j = 0; j < 4; j++) {
            float* p = outb + (size_t)(q0 + wm * 32 + i * 16) * PQ + n0 + wn * 64 + j * 16;
            wmma::store_matrix_sync(p, acc[i][j], PQ, wmma::mem_row_major);
        }
}

// ---------------- 7) epilogue: per-(b,q), 4 d per thread, float4 stores ----------------
__global__ __launch_bounds__(256) void k_epilogue(const float* __restrict__ Wout,
                                                  float* __restrict__ out) {
    __shared__ float As[16][516];
    int q = blockIdx.x;
    int b = blockIdx.y;
    int tid = threadIdx.x;
#pragma unroll
    for (int it = 0; it < 8; it++) {
        int idx = it * 256 + tid;          // 2048 float4 = 16h x 128
        int h = idx >> 7, k4 = idx & 127;
        float4 v = *(const float4*)(g_dot + ((size_t)(b * NH + h) * PQ + q) * PQ + k4 * 4);
        *(float4*)&As[h][k4 * 4] = v;
    }
    __syncthreads();

    int d0   = (tid & 15) * 4;             // 4 consecutive d
    int kgrp = tid >> 4;                   // 0..15
    float4 w[16];
#pragma unroll
    for (int h = 0; h < 16; h++)
        w[h] = make_float4(Wout[(d0 + 0) * 16 + h], Wout[(d0 + 1) * 16 + h],
                           Wout[(d0 + 2) * 16 + h], Wout[(d0 + 3) * 16 + h]);

    size_t rowq = (size_t)b * PQ + q;
    float4 rqA = *(const float4*)(g_RqA + rowq * 64 + d0);
    float4 rqB = *(const float4*)(g_RqB + rowq * 64 + d0);
    const float* ckb = (q == PQ - 1 ? g_CkB : g_CkA) + (size_t)b * PQ * 64;
    float* obase = out + rowq * PQ * 64;

#pragma unroll 4
    for (int i = 0; i < 32; i++) {
        int k = kgrp + 16 * i;
        float4 acc = make_float4(0.f, 0.f, 0.f, 0.f);
#pragma unroll
        for (int h = 0; h < 16; h++) {
            float a = As[h][k];
            acc.x += a * w[h].x;
            acc.y += a * w[h].y;
            acc.z += a * w[h].z;
            acc.w += a * w[h].w;
        }
        float4 rq = (k == PQ - 1) ? rqB : rqA;
        float4 ck = *(const float4*)(ckb + (size_t)k * 64 + d0);
        float4 o;
        o.x = acc.x + rq.x + ck.x;
        o.y = acc.y + rq.y + ck.y;
        o.z = acc.z + rq.z + ck.z;
        o.w = acc.w + rq.w + ck.w;
        *(float4*)(obase + (size_t)k * 64 + d0) = o;
    }
}

extern "C" void kernel_launch(void* const* d_in, const int* in_sizes, int n_in,
                              void* d_out, int out_size) {
    const float* x    = (const float*)d_in[0];
    const float* Wq   = (const float*)d_in[1];
    const float* Wk   = (const float*)d_in[2];
    const float* Wpos = (const float*)d_in[3];
    const float* bpos = (const float*)d_in[4];
    const float* qb   = (const float*)d_in[5];
    const float* kb   = (const float*)d_in[6];
    const float* Wout = (const float*)d_in[7];
    const float* bout = (const float*)d_in[8];
    const float* Wyq  = (const float*)d_in[9];
    const float* Wyk  = (const float*)d_in[10];
    float* out = (float*)d_out;
    (void)in_sizes; (void)n_in; (void)out_size;

    cudaFuncSetAttribute(k_projmma, cudaFuncAttributeMaxDynamicSharedMemorySize, GEMM_SMEM);
    cudaFuncSetAttribute(k_dot,     cudaFuncAttributeMaxDynamicSharedMemorySize, DOT_SMEM);

    k_pool   <<<2048, 256>>>(x);
    k_posenc <<<4, 256>>>(Wpos, bpos);
    k_split1 <<<dim3(2048, 1, 3), 256>>>(Wq, Wk);
    k_projmma<<<dim3(8, 16, 2), 256, GEMM_SMEM>>>();
    k_y      <<<dim3(8, 16), 256>>>(Wyq, Wyk);
    k_scalars<<<dim3(2048, 2), 64>>>(qb, kb, Wout, bout);
    k_dot    <<<dim3(4, 4, 64), 256, DOT_SMEM>>>();
    k_epilogue<<<dim3(512, 4), 256>>>(Wout, out);
}